// round 15
// baseline (speedup 1.0000x reference)
#include <cuda_runtime.h>
#include <cstddef>
#include <cstdint>

#define NPTS 1000000
#define KSZ 9
#define EPSBN 1e-5f
#define NF4 (NPTS * 16 / 4)
#define CONVGRID 7813             // 128 points per block (last block partial)
#define MIDB 64
#define RPB ((CONVGRID + MIDB - 1) / MIDB)
#define SGRID 1184
#define SSTRIDE (SGRID * 256)

// dynamic smem layout (bytes):
//   [0, 73728)        sdat: [9 j][4 u][128 p] float4  (3 chunks of 3 j)
//   [73728, 82944)    wsm:  [j][c][o] floats (2304)
//   [82944, 87552)    sind: 1152 ints
#define SDAT_BYTES 73728
#define WSM_OFF    73728
#define SIND_OFF   82944
#define CONV_SMEM  87552

typedef unsigned long long ull;

// ---------------- scratch (device globals: no allocation) ----------------
__device__ float g_h[(size_t)NPTS * 16];           // conv1 raw output, 64 MB
__device__ float4 g_part4[CONVGRID * 8];           // per-block stats partials
__device__ float g_mid[MIDB * 32];
__device__ __align__(16) float g_st1[32];          // BN1 scale[16], shift[16]
__device__ __align__(16) float g_st2[32];          // BN2 scale[16], shift[16]

// ---------------- f32x2 packed helpers ----------------
__device__ __forceinline__ ull pack2(float lo, float hi) {
    ull r; asm("mov.b64 %0, {%1, %2};" : "=l"(r) : "f"(lo), "f"(hi)); return r;
}
__device__ __forceinline__ void unpack2(ull v, float& lo, float& hi) {
    asm("mov.b64 {%0, %1}, %2;" : "=f"(lo), "=f"(hi) : "l"(v));
}
__device__ __forceinline__ ull fma2(ull a, ull b, ull c) {
    ull d; asm("fma.rn.f32x2 %0, %1, %2, %3;" : "=l"(d) : "l"(a), "l"(b), "l"(c)); return d;
}

// =====================================================================
// Tree-conv: thread-per-point, self-staged cp.async pipeline.
//  - thread t owns point pbase+t; stages ITS OWN 9 rows (36 x 16B cp.async,
//    3 commit groups of 3 j each) and consumes only what it staged ->
//    wait_group is thread-local, NO syncthreads in the mainloop.
//  - A reads: [j][u][p] float4, lanes p consecutive -> conflict-free
//  - W reads: identical address warp-wide -> smem broadcast (N=1)
//  - f32x2 over output-channel pairs, 8 independent accumulators
//  - per-block BN stats (sum, sumsq per channel) reduced at the end
// =====================================================================
template <bool BIAS>
__global__ void __launch_bounds__(128) conv_kernel(
    const float* __restrict__ src, const int* __restrict__ ind,
    const float* __restrict__ w, const float* __restrict__ bias,
    float* __restrict__ dst)
{
    extern __shared__ __align__(16) unsigned char dynsmem[];
    float4* sdat = reinterpret_cast<float4*>(dynsmem);
    float*  wsm  = reinterpret_cast<float*>(dynsmem + WSM_OFF);
    int*    sind = reinterpret_cast<int*>(dynsmem + SIND_OFF);

    const int tid = threadIdx.x;
    const int pt = blockIdx.x * 128 + tid;
    const bool valid = pt < NPTS;

    // ---- stage weights: w[c][o][j] -> wsm[j][c][o] ----
    for (int i = tid; i < 16 * 16 * KSZ; i += 128) {
        int c = i / 144;
        int rem = i - c * 144;
        int o = rem / 9;
        int j = rem - o * 9;
        wsm[(j * 16 + c) * 16 + o] = w[i];
    }
    // ---- stage indices (coalesced); clamp out-of-range to 0 ----
    {
        const int base = blockIdx.x * 1152;
#pragma unroll
        for (int r = 0; r < 9; r++) {
            int i = tid + 128 * r;
            int gi = base + i;
            sind[i] = (gi < NPTS * KSZ) ? __ldg(ind + gi) : 0;
        }
    }
    __syncthreads();

    const float4* sp = reinterpret_cast<const float4*>(src);
    const uint32_t sbase = (uint32_t)__cvta_generic_to_shared(sdat);

    // ---- stage all 3 chunks (9 rows, 36 cp.async, 3 groups) ----
#pragma unroll
    for (int ch = 0; ch < 3; ch++) {
#pragma unroll
        for (int jl = 0; jl < 3; jl++) {
            const int j = ch * 3 + jl;
            const int row = sind[tid * 9 + j];
            const float4* gsrc = sp + (size_t)row * 4;
#pragma unroll
            for (int u = 0; u < 4; u++) {
                uint32_t sa = sbase + (uint32_t)(((j * 4 + u) * 128 + tid) * 16);
                asm volatile("cp.async.cg.shared.global [%0], [%1], 16;"
                             :: "r"(sa), "l"(gsrc + u));
            }
        }
        asm volatile("cp.async.commit_group;");
    }

    ull acc[8];
#pragma unroll
    for (int i = 0; i < 8; i++) acc[i] = 0ull;

    // ---- compute chunk by chunk; thread-local waits, no block sync ----
#pragma unroll
    for (int ch = 0; ch < 3; ch++) {
        if (ch == 0) asm volatile("cp.async.wait_group 2;" ::: "memory");
        else if (ch == 1) asm volatile("cp.async.wait_group 1;" ::: "memory");
        else asm volatile("cp.async.wait_group 0;" ::: "memory");

#pragma unroll
        for (int jl = 0; jl < 3; jl++) {
            const int j = ch * 3 + jl;
            float4 A[4];
#pragma unroll
            for (int u = 0; u < 4; u++) A[u] = sdat[(j * 4 + u) * 128 + tid];
            const float* wj = wsm + j * 256;
#pragma unroll
            for (int c = 0; c < 16; c++) {
                const float v = (&A[c >> 2].x)[c & 3];
                const ull vp = pack2(v, v);
                const ulonglong2* wv = reinterpret_cast<const ulonglong2*>(wj + c * 16);
                ulonglong2 w0 = wv[0];     // broadcast addresses warp-wide
                ulonglong2 w1 = wv[1];
                acc[0] = fma2(vp, w0.x, acc[0]);
                acc[1] = fma2(vp, w0.y, acc[1]);
                acc[2] = fma2(vp, w1.x, acc[2]);
                acc[3] = fma2(vp, w1.y, acc[3]);
                ulonglong2 w2 = wv[2];
                ulonglong2 w3 = wv[3];
                acc[4] = fma2(vp, w2.x, acc[4]);
                acc[5] = fma2(vp, w2.y, acc[5]);
                acc[6] = fma2(vp, w3.x, acc[6]);
                acc[7] = fma2(vp, w3.y, acc[7]);
            }
        }
    }

    // ---- bias, store, per-point stats ----
    float o[16];
#pragma unroll
    for (int i = 0; i < 8; i++) unpack2(acc[i], o[2 * i], o[2 * i + 1]);
    if (BIAS) {
#pragma unroll
        for (int cg = 0; cg < 4; cg++) {
            float4 b4 = reinterpret_cast<const float4*>(bias)[cg];
            o[4 * cg + 0] += b4.x; o[4 * cg + 1] += b4.y;
            o[4 * cg + 2] += b4.z; o[4 * cg + 3] += b4.w;
        }
    }
    if (valid) {
        float4* op = reinterpret_cast<float4*>(dst) + (size_t)pt * 4;
        op[0] = make_float4(o[0], o[1], o[2], o[3]);
        op[1] = make_float4(o[4], o[5], o[6], o[7]);
        op[2] = make_float4(o[8], o[9], o[10], o[11]);
        op[3] = make_float4(o[12], o[13], o[14], o[15]);
    } else {
#pragma unroll
        for (int c = 0; c < 16; c++) o[c] = 0.f;
    }

    // ---- per-block stats reduce (reuse sdat; deterministic) ----
    __syncthreads();                        // everyone done reading sdat
    float4* r1 = reinterpret_cast<float4*>(dynsmem);          // 512 float4
    float4* r2 = r1 + 512;                                     // 512 float4
#pragma unroll
    for (int cg = 0; cg < 4; cg++) {
        r1[tid * 4 + cg] = make_float4(o[4 * cg], o[4 * cg + 1],
                                       o[4 * cg + 2], o[4 * cg + 3]);
        r2[tid * 4 + cg] = make_float4(o[4 * cg] * o[4 * cg],
                                       o[4 * cg + 1] * o[4 * cg + 1],
                                       o[4 * cg + 2] * o[4 * cg + 2],
                                       o[4 * cg + 3] * o[4 * cg + 3]);
    }
    __syncthreads();
#pragma unroll
    for (int off = 64; off >= 1; off >>= 1) {
        if (tid < off) {
#pragma unroll
            for (int cg = 0; cg < 4; cg++) {
                float4 a = r1[tid * 4 + cg], b = r1[(tid + off) * 4 + cg];
                a.x += b.x; a.y += b.y; a.z += b.z; a.w += b.w;
                r1[tid * 4 + cg] = a;
                float4 c = r2[tid * 4 + cg], d = r2[(tid + off) * 4 + cg];
                c.x += d.x; c.y += d.y; c.z += d.z; c.w += d.w;
                r2[tid * 4 + cg] = c;
            }
        }
        __syncthreads();
    }
    if (tid < 4) {
        g_part4[blockIdx.x * 8 + tid] = r1[tid];       // channel sums
        g_part4[blockIdx.x * 8 + 4 + tid] = r2[tid];   // channel squares
    }
}

// ---------------- BN1 + leaky applied in place on g_h ----------------
__global__ __launch_bounds__(256) void bnapply_kernel()
{
    const int tid = threadIdx.x;
    const int idx = blockIdx.x * 256 + tid;
    const int g = tid & 3;
    float4 sc = reinterpret_cast<const float4*>(g_st1)[g];
    float4 sh = reinterpret_cast<const float4*>(g_st1 + 16)[g];
    float4* hh = reinterpret_cast<float4*>(g_h);
    for (int i = idx; i < NF4; i += SSTRIDE) {
        float4 v = hh[i];
        v.x = fmaf(v.x, sc.x, sh.x); v.x = fmaxf(v.x, 0.2f * v.x);
        v.y = fmaf(v.y, sc.y, sh.y); v.y = fmaxf(v.y, 0.2f * v.y);
        v.z = fmaf(v.z, sc.z, sh.z); v.z = fmaxf(v.z, 0.2f * v.z);
        v.w = fmaf(v.w, sc.w, sh.w); v.w = fmaxf(v.w, 0.2f * v.w);
        hh[i] = v;
    }
}

// ---------------- mid-stage stats reduction: CONVGRID -> 64 partials ----------------
__global__ __launch_bounds__(256) void midstats_kernel()
{
    const float* part = reinterpret_cast<const float*>(g_part4);
    const int tid = threadIdx.x;
    const int v = tid & 31;
    const int lane = tid >> 5;
    const int r0 = blockIdx.x * RPB;
    const int rend = min(r0 + RPB, CONVGRID);
    float loc = 0.f;
    for (int r = r0 + lane; r < rend; r += 8) loc += part[r * 32 + v];
    __shared__ float sm[256];
    sm[tid] = loc;
    __syncthreads();
    if (tid < 32) {
        float t = 0.f;
#pragma unroll
        for (int k = 0; k < 8; k++) t += sm[tid + k * 32];
        g_mid[blockIdx.x * 32 + tid] = t;
    }
}

// ---------------- finalize: 64 partials -> BN scale/shift ----------------
template <int S>
__global__ void finalize_kernel(const float* __restrict__ gamma,
                                const float* __restrict__ beta)
{
    const int tid = threadIdx.x;   // 32 threads
    __shared__ float sm[32];
    float t = 0.f;
    for (int r = 0; r < MIDB; r++) t += g_mid[r * 32 + tid];
    sm[tid] = t;
    __syncthreads();
    if (tid < 16) {
        const float inv_n = 1.0f / (float)NPTS;
        float mean = sm[tid] * inv_n;
        float var = sm[16 + tid] * inv_n - mean * mean;
        float rstd = rsqrtf(var + EPSBN);
        float sc = gamma[tid] * rstd;
        float sh = beta[tid] - mean * sc;
        float* st = (S == 1) ? g_st1 : g_st2;
        st[tid] = sc;
        st[16 + tid] = sh;
    }
}

// ---------- epilogue: out = leaky(BN2(raw2) + data), in place on d_out ----------
__global__ __launch_bounds__(256) void bnres_kernel(
    const float* __restrict__ data, float* __restrict__ out)
{
    const int tid = threadIdx.x;
    const int idx = blockIdx.x * 256 + tid;
    const int g = tid & 3;
    float4 sc = reinterpret_cast<const float4*>(g_st2)[g];
    float4 sh = reinterpret_cast<const float4*>(g_st2 + 16)[g];
    const float4* dd = reinterpret_cast<const float4*>(data);
    float4* oo = reinterpret_cast<float4*>(out);
    for (int i = idx; i < NF4; i += SSTRIDE) {
        float4 r = oo[i];
        float4 d = dd[i];
        float4 y;
        y.x = fmaf(r.x, sc.x, sh.x) + d.x;
        y.y = fmaf(r.y, sc.y, sh.y) + d.y;
        y.z = fmaf(r.z, sc.z, sh.z) + d.z;
        y.w = fmaf(r.w, sc.w, sh.w) + d.w;
        y.x = fmaxf(y.x, 0.2f * y.x);
        y.y = fmaxf(y.y, 0.2f * y.y);
        y.z = fmaxf(y.z, 0.2f * y.z);
        y.w = fmaxf(y.w, 0.2f * y.w);
        oo[i] = y;
    }
}

extern "C" void kernel_launch(void* const* d_in, const int* in_sizes, int n_in,
                              void* d_out, int out_size)
{
    const float* data   = (const float*)d_in[0];
    const int*   ind    = (const int*)  d_in[1];
    const float* w1     = (const float*)d_in[2];
    const float* b1     = (const float*)d_in[3];
    const float* gamma1 = (const float*)d_in[4];
    const float* beta1  = (const float*)d_in[5];
    const float* w2     = (const float*)d_in[6];
    const float* gamma2 = (const float*)d_in[7];
    const float* beta2  = (const float*)d_in[8];
    float* out = (float*)d_out;

    float* gh;
    cudaGetSymbolAddress((void**)&gh, g_h);

    cudaFuncSetAttribute(conv_kernel<true>,
                         cudaFuncAttributeMaxDynamicSharedMemorySize, CONV_SMEM);
    cudaFuncSetAttribute(conv_kernel<false>,
                         cudaFuncAttributeMaxDynamicSharedMemorySize, CONV_SMEM);

    conv_kernel<true><<<CONVGRID, 128, CONV_SMEM>>>(data, ind, w1, b1, gh);
    midstats_kernel<<<MIDB, 256>>>();
    finalize_kernel<1><<<1, 32>>>(gamma1, beta1);
    bnapply_kernel<<<SGRID, 256>>>();                      // BN1+leaky on g_h
    conv_kernel<false><<<CONVGRID, 128, CONV_SMEM>>>(gh, ind, w2, nullptr, out);
    midstats_kernel<<<MIDB, 256>>>();
    finalize_kernel<2><<<1, 32>>>(gamma2, beta2);
    bnres_kernel<<<SGRID, 256>>>(data, out);
}

// round 16
// speedup vs baseline: 2.3896x; 2.3896x over previous
#include <cuda_runtime.h>
#include <cstddef>
#include <cstdint>

#define NPTS 1000000
#define KSZ 9
#define EPSBN 1e-5f
#define NF4 (NPTS * 16 / 4)
#define CONVGRID 3907             // 256 points per block (last block partial)
#define MIDB 64
#define RPB ((CONVGRID + MIDB - 1) / MIDB)
#define SGRID 1184
#define SSTRIDE (SGRID * 256)

typedef unsigned long long ull;

// ---------------- scratch (device globals: no allocation) ----------------
__device__ float g_h[(size_t)NPTS * 16];           // conv1 raw output, 64 MB
__device__ float4 g_part4[CONVGRID * 8];           // per-block stats partials
__device__ float g_mid[MIDB * 32];
__device__ __align__(16) float g_st1[32];          // BN1 scale[16], shift[16]
__device__ __align__(16) float g_st2[32];          // BN2 scale[16], shift[16]

// ---------------- f32x2 packed helpers ----------------
__device__ __forceinline__ ull pack2(float lo, float hi) {
    ull r; asm("mov.b64 %0, {%1, %2};" : "=l"(r) : "f"(lo), "f"(hi)); return r;
}
__device__ __forceinline__ void unpack2(ull v, float& lo, float& hi) {
    asm("mov.b64 {%0, %1}, %2;" : "=f"(lo), "=f"(hi) : "l"(v));
}
__device__ __forceinline__ ull fma2(ull a, ull b, ull c) {
    ull d; asm("fma.rn.f32x2 %0, %1, %2, %3;" : "=l"(d) : "l"(a), "l"(b), "l"(c)); return d;
}
__device__ __forceinline__ ull add2(ull a, ull b) {
    ull d; asm("add.rn.f32x2 %0, %1, %2;" : "=l"(d) : "l"(a), "l"(b)); return d;
}

// =====================================================================
// Fused tree-conv (R4 configuration — measured 177us without inline BN).
//  - 4 lanes per point-column (lane g owns input channels 4g..4g+3)
//  - 4 points per thread (n = pbase + G + 64k)
//  - weights NOT duplicated: f32x2 packs output-channel pairs; the value
//    is duplicated in-register ((v,v)); bank-skewed smem
//  - coalesced gather: one LDG.128 per lane = 16B chunk of a 64B row
//  - reduce-scatter over the 4-lane group -> lane g holds o=4g..4g+3
//  - per-block BN stats (sum, sumsq per channel) fused at the end
//  BN1+leaky is applied by a separate 17us elementwise pass (bnapply),
//  NOT inline — inline BNAPP costs 9x per point (measured +49us).
// =====================================================================
template <bool BIAS>
__global__ void __launch_bounds__(256) conv_kernel(
    const float* __restrict__ src, const int* __restrict__ ind,
    const float* __restrict__ w, const float* __restrict__ bias,
    float* __restrict__ dst)
{
    // ws[g][j][cc][o]: g-stride 580 floats (580 mod 32 = 4 -> 4 group
    // addresses on disjoint banks). Reused for stats reduction (needs 2048).
    __shared__ __align__(16) float ws[4 * 580];
    const int tid = threadIdx.x;
    const int g = tid & 3;
    const int G = tid >> 2;

    for (int i = tid; i < 16 * 16 * KSZ; i += 256) {
        int c = i / 144;
        int rem = i - c * 144;
        int o = rem / 9;
        int j = rem - o * 9;
        ws[(c >> 2) * 580 + j * 64 + (c & 3) * 16 + o] = w[i];
    }
    __syncthreads();

    const int pbase = blockIdx.x * 256;
    int npt[4]; bool vld[4];
#pragma unroll
    for (int k = 0; k < 4; k++) {
        npt[k] = pbase + G + 64 * k;
        vld[k] = npt[k] < NPTS;
    }

    ull acc[4][8];
#pragma unroll
    for (int k = 0; k < 4; k++)
#pragma unroll
        for (int p = 0; p < 8; p++) acc[k][p] = 0ull;

    const float4* sp = reinterpret_cast<const float4*>(src);
    const float* wg = ws + g * 580;

#pragma unroll
    for (int j = 0; j < KSZ; j++) {
        float4 a[4];
#pragma unroll
        for (int k = 0; k < 4; k++) {
            if (vld[k]) {
                int rk = __ldg(ind + npt[k] * KSZ + j);
                a[k] = __ldg(sp + (size_t)rk * 4 + g);
            } else {
                a[k] = make_float4(0.f, 0.f, 0.f, 0.f);
            }
        }
        const ulonglong2* wj = reinterpret_cast<const ulonglong2*>(wg + j * 64);
#pragma unroll
        for (int cc = 0; cc < 4; cc++) {
            // 16 weight floats (o0..15) = 8 f32x2 pairs, shared by 4 points
            ulonglong2 w0 = wj[cc * 4 + 0];
            ulonglong2 w1 = wj[cc * 4 + 1];
            ulonglong2 w2 = wj[cc * 4 + 2];
            ulonglong2 w3 = wj[cc * 4 + 3];
#pragma unroll
            for (int k = 0; k < 4; k++) {
                const float v = (cc == 0) ? a[k].x : (cc == 1) ? a[k].y
                              : (cc == 2) ? a[k].z : a[k].w;
                const ull v2 = pack2(v, v);
                acc[k][0] = fma2(v2, w0.x, acc[k][0]);
                acc[k][1] = fma2(v2, w0.y, acc[k][1]);
                acc[k][2] = fma2(v2, w1.x, acc[k][2]);
                acc[k][3] = fma2(v2, w1.y, acc[k][3]);
                acc[k][4] = fma2(v2, w2.x, acc[k][4]);
                acc[k][5] = fma2(v2, w2.y, acc[k][5]);
                acc[k][6] = fma2(v2, w3.x, acc[k][6]);
                acc[k][7] = fma2(v2, w3.y, acc[k][7]);
            }
        }
    }

    // reduce-scatter per point; accumulate block stats
    float4 s4 = make_float4(0.f, 0.f, 0.f, 0.f);
    float4 q4 = make_float4(0.f, 0.f, 0.f, 0.f);
    float4 b4;
    if (BIAS) b4 = reinterpret_cast<const float4*>(bias)[g];

#pragma unroll
    for (int k = 0; k < 4; k++) {
        // stage A (xor 2): pairs 0..3 = o0..7 stay with g<2; 4..7 with g>=2
        ull h4[4];
#pragma unroll
        for (int i = 0; i < 4; i++) {
            ull aa = acc[k][i], bb = acc[k][i + 4];
            ull mine = (g & 2) ? aa : bb;
            ull oth = __shfl_xor_sync(0xffffffffu, mine, 2);
            h4[i] = add2((g & 2) ? bb : aa, oth);
        }
        // stage B (xor 1): even g keeps lower 2 pairs of its half
        ull q2[2];
#pragma unroll
        for (int i = 0; i < 2; i++) {
            ull aa = h4[i], bb = h4[i + 2];
            ull mine = (g & 1) ? aa : bb;
            ull oth = __shfl_xor_sync(0xffffffffu, mine, 1);
            q2[i] = add2((g & 1) ? bb : aa, oth);
        }
        float o0, o1, o2, o3;
        unpack2(q2[0], o0, o1);
        unpack2(q2[1], o2, o3);
        if (BIAS) { o0 += b4.x; o1 += b4.y; o2 += b4.z; o3 += b4.w; }
        if (vld[k]) {
            reinterpret_cast<float4*>(dst)[(size_t)npt[k] * 4 + g] =
                make_float4(o0, o1, o2, o3);
            s4.x += o0; s4.y += o1; s4.z += o2; s4.w += o3;
            q4.x += o0 * o0; q4.y += o1 * o1; q4.z += o2 * o2; q4.w += o3 * o3;
        }
    }

    // ---- fused per-block BN stats (deterministic), reuse weight smem ----
    __syncthreads();
    float4* s1 = reinterpret_cast<float4*>(ws);        // 256 float4
    float4* s2 = s1 + 256;
    s1[tid] = s4; s2[tid] = q4;
    __syncthreads();
#pragma unroll
    for (int off = 128; off >= 4; off >>= 1) {
        if (tid < off) {
            float4 a = s1[tid], b = s1[tid + off];
            a.x += b.x; a.y += b.y; a.z += b.z; a.w += b.w; s1[tid] = a;
            float4 c = s2[tid], d = s2[tid + off];
            c.x += d.x; c.y += d.y; c.z += d.z; c.w += d.w; s2[tid] = c;
        }
        __syncthreads();
    }
    if (tid < 4) {
        g_part4[blockIdx.x * 8 + tid] = s1[tid];
        g_part4[blockIdx.x * 8 + 4 + tid] = s2[tid];
    }
}

// ---------------- BN1 + leaky applied in place on g_h ----------------
__global__ __launch_bounds__(256) void bnapply_kernel()
{
    const int tid = threadIdx.x;
    const int idx = blockIdx.x * 256 + tid;
    const int g = tid & 3;
    float4 sc = reinterpret_cast<const float4*>(g_st1)[g];
    float4 sh = reinterpret_cast<const float4*>(g_st1 + 16)[g];
    float4* hh = reinterpret_cast<float4*>(g_h);
    for (int i = idx; i < NF4; i += SSTRIDE) {
        float4 v = hh[i];
        v.x = fmaf(v.x, sc.x, sh.x); v.x = fmaxf(v.x, 0.2f * v.x);
        v.y = fmaf(v.y, sc.y, sh.y); v.y = fmaxf(v.y, 0.2f * v.y);
        v.z = fmaf(v.z, sc.z, sh.z); v.z = fmaxf(v.z, 0.2f * v.z);
        v.w = fmaf(v.w, sc.w, sh.w); v.w = fmaxf(v.w, 0.2f * v.w);
        hh[i] = v;
    }
}

// ---------------- mid-stage stats reduction: CONVGRID -> 64 partials ----------------
__global__ __launch_bounds__(256) void midstats_kernel()
{
    const float* part = reinterpret_cast<const float*>(g_part4);
    const int tid = threadIdx.x;
    const int v = tid & 31;
    const int lane = tid >> 5;
    const int r0 = blockIdx.x * RPB;
    const int rend = min(r0 + RPB, CONVGRID);
    float loc = 0.f;
    for (int r = r0 + lane; r < rend; r += 8) loc += part[r * 32 + v];
    __shared__ float sm[256];
    sm[tid] = loc;
    __syncthreads();
    if (tid < 32) {
        float t = 0.f;
#pragma unroll
        for (int k = 0; k < 8; k++) t += sm[tid + k * 32];
        g_mid[blockIdx.x * 32 + tid] = t;
    }
}

// ---------------- finalize: 64 partials -> BN scale/shift ----------------
template <int S>
__global__ void finalize_kernel(const float* __restrict__ gamma,
                                const float* __restrict__ beta)
{
    const int tid = threadIdx.x;   // 32 threads
    __shared__ float sm[32];
    float t = 0.f;
    for (int r = 0; r < MIDB; r++) t += g_mid[r * 32 + tid];
    sm[tid] = t;
    __syncthreads();
    if (tid < 16) {
        const float inv_n = 1.0f / (float)NPTS;
        float mean = sm[tid] * inv_n;
        float var = sm[16 + tid] * inv_n - mean * mean;
        float rstd = rsqrtf(var + EPSBN);
        float sc = gamma[tid] * rstd;
        float sh = beta[tid] - mean * sc;
        float* st = (S == 1) ? g_st1 : g_st2;
        st[tid] = sc;
        st[16 + tid] = sh;
    }
}

// ---------- epilogue: out = leaky(BN2(raw2) + data), in place on d_out ----------
__global__ __launch_bounds__(256) void bnres_kernel(
    const float* __restrict__ data, float* __restrict__ out)
{
    const int tid = threadIdx.x;
    const int idx = blockIdx.x * 256 + tid;
    const int g = tid & 3;
    float4 sc = reinterpret_cast<const float4*>(g_st2)[g];
    float4 sh = reinterpret_cast<const float4*>(g_st2 + 16)[g];
    const float4* dd = reinterpret_cast<const float4*>(data);
    float4* oo = reinterpret_cast<float4*>(out);
    for (int i = idx; i < NF4; i += SSTRIDE) {
        float4 r = oo[i];
        float4 d = dd[i];
        float4 y;
        y.x = fmaf(r.x, sc.x, sh.x) + d.x;
        y.y = fmaf(r.y, sc.y, sh.y) + d.y;
        y.z = fmaf(r.z, sc.z, sh.z) + d.z;
        y.w = fmaf(r.w, sc.w, sh.w) + d.w;
        y.x = fmaxf(y.x, 0.2f * y.x);
        y.y = fmaxf(y.y, 0.2f * y.y);
        y.z = fmaxf(y.z, 0.2f * y.z);
        y.w = fmaxf(y.w, 0.2f * y.w);
        oo[i] = y;
    }
}

extern "C" void kernel_launch(void* const* d_in, const int* in_sizes, int n_in,
                              void* d_out, int out_size)
{
    const float* data   = (const float*)d_in[0];
    const int*   ind    = (const int*)  d_in[1];
    const float* w1     = (const float*)d_in[2];
    const float* b1     = (const float*)d_in[3];
    const float* gamma1 = (const float*)d_in[4];
    const float* beta1  = (const float*)d_in[5];
    const float* w2     = (const float*)d_in[6];
    const float* gamma2 = (const float*)d_in[7];
    const float* beta2  = (const float*)d_in[8];
    float* out = (float*)d_out;

    float* gh;
    cudaGetSymbolAddress((void**)&gh, g_h);

    conv_kernel<true><<<CONVGRID, 256>>>(data, ind, w1, b1, gh);
    midstats_kernel<<<MIDB, 256>>>();
    finalize_kernel<1><<<1, 32>>>(gamma1, beta1);
    bnapply_kernel<<<SGRID, 256>>>();                      // BN1+leaky on g_h
    conv_kernel<false><<<CONVGRID, 256>>>(gh, ind, w2, nullptr, out);
    midstats_kernel<<<MIDB, 256>>>();
    finalize_kernel<2><<<1, 32>>>(gamma2, beta2);
    bnres_kernel<<<SGRID, 256>>>(data, out);
}